// round 12
// baseline (speedup 1.0000x reference)
#include <cuda_runtime.h>
#include <math.h>
#include <cstdint>

#define BB 64
#define DIM 640
#define MK 100
#define NKS 13
#define TT 128
#define NT 5            // DIM / TT
#define NPAIR 15        // upper tile pairs
#define TRI 205120      // 640*641/2
#define EPSV 1e-5f
#define SPAD 104        // EVEN stride: LDS.64 frag loads conflict-free (gid*8 bank cycle)
#define TSZ (TT * SPAD)
#define NROWS (BB * DIM)

// ---- scratch (static device arrays: allocation-free) ----
__device__ float g_sp[NT][BB][DIM];   // row-sum slots (exactly-once writes)
__device__ float g_d[NROWS];          // squared norms
__device__ float g_sb[NROWS];         // per-batch row sums, pre-scaled by 1/dim
__device__ float g_gm[BB];            // per-batch grand mean

// ---------------------------------------------------------------------------
__device__ __forceinline__ uint32_t f2tf32(float v) {
    uint32_t r;
    asm("cvt.rna.tf32.f32 %0, %1;" : "=r"(r) : "f"(v));
    return r;
}
__device__ __forceinline__ void mma8(float* c, const uint32_t* a, const uint32_t* b) {
    asm volatile(
        "mma.sync.aligned.m16n8k8.row.col.f32.tf32.tf32.f32 "
        "{%0,%1,%2,%3}, {%4,%5,%6,%7}, {%8,%9}, {%0,%1,%2,%3};"
        : "+f"(c[0]), "+f"(c[1]), "+f"(c[2]), "+f"(c[3])
        : "r"(a[0]), "r"(a[1]), "r"(a[2]), "r"(a[3]), "r"(b[0]), "r"(b[1]));
}
// permuted position of k within its block of 8: order [0,4,1,5,2,6,3,7]
__device__ __forceinline__ int kperm(int k) {
    return (k & ~7) + 2 * (k & 3) + ((k & 7) >> 2);
}

// ---------------------------------------------------------------------------
// Norms: one warp per x-row (coalesced), split over batch thirds
// ---------------------------------------------------------------------------
__global__ void norm_kernel(const float* __restrict__ x, int row0, int nrows) {
    int w = (blockIdx.x * 256 + threadIdx.x) >> 5;
    int lane = threadIdx.x & 31;
    if (w >= nrows) return;
    const float* xr = x + (size_t)(row0 + w) * MK;
    float s = 0.f;
#pragma unroll
    for (int k = lane; k < MK; k += 32) { float v = xr[k]; s = fmaf(v, v, s); }
#pragma unroll
    for (int o = 16; o >= 1; o >>= 1) s += __shfl_xor_sync(0xffffffffu, s, o);
    if (lane == 0) g_d[row0 + w] = s;
}

// ---------------------------------------------------------------------------
// Gram: smem-pre-split tf32 hi/lo tiles, pure LDS+HMMA mainloop.
// 1024 threads (32 warps, 16x32 warp tiles), 1 CTA/SM.
// ---------------------------------------------------------------------------
__global__ __launch_bounds__(1024, 1)
void gram_dcov_kernel(const float* __restrict__ x, const float* __restrict__ t,
                      float* __restrict__ out) {
    int p = blockIdx.x, b = blockIdx.y;
    int ti = 0, rem = p;
    while (rem >= NT - ti) { rem -= NT - ti; ti++; }
    int tj = ti + rem;
    int i0 = ti * TT, j0 = tj * TT;
    bool diag = (ti == tj);

    extern __shared__ float sm[];
    float* Ahi = sm;
    float* Alo = Ahi + TSZ;
    float* Bhi = Alo + TSZ;
    float* Blo = Bhi + TSZ;

    __shared__ float di_s[TT], dj_s[TT], rs_s[TT], cs_s[TT];

    int tid = threadIdx.x;
    if (tid < TT) { rs_s[tid] = 0.f; cs_s[tid] = 0.f; }

    const float* xb = x + (size_t)b * DIM * MK;

    // ---- stage: fp32 -> (tf32 hi, exact fp32 lo) into permuted-k tiles ----
    {
        const float* srcA = xb + (size_t)i0 * MK;
        for (int idx = tid; idx < TT * SPAD; idx += 1024) {
            int r = idx / SPAD, k = idx - r * SPAD;
            float v = (k < MK) ? srcA[r * MK + k] : 0.f;
            uint32_t h = f2tf32(v);
            int d = r * SPAD + kperm(k);
            Ahi[d] = __uint_as_float(h);
            Alo[d] = v - __uint_as_float(h);
        }
        if (!diag) {
            const float* srcB = xb + (size_t)j0 * MK;
            for (int idx = tid; idx < TT * SPAD; idx += 1024) {
                int r = idx / SPAD, k = idx - r * SPAD;
                float v = (k < MK) ? srcB[r * MK + k] : 0.f;
                uint32_t h = f2tf32(v);
                int d = r * SPAD + kperm(k);
                Bhi[d] = __uint_as_float(h);
                Blo[d] = v - __uint_as_float(h);
            }
        }
    }
    // preload norms (L2-hot)
    {
        const float* dbase = g_d + b * DIM;
        if (tid < TT) di_s[tid] = dbase[i0 + tid];
        else if (tid < 2 * TT) dj_s[tid - TT] = dbase[j0 + (tid - TT)];
    }
    const float* BhP = diag ? Ahi : Bhi;
    const float* BlP = diag ? Alo : Blo;
    __syncthreads();

    // warp layout: 8(m) x 4(n); warp tile 16 rows x 32 cols
    int wid = tid >> 5, lane = tid & 31;
    int wm = wid >> 2, wn = wid & 3;
    int gid = lane >> 2, tig = lane & 3;

    float acc[4][4];
#pragma unroll
    for (int nt = 0; nt < 4; nt++)
#pragma unroll
        for (int q = 0; q < 4; q++) acc[nt][q] = 0.f;

    const float* ahp = Ahi + (wm * 16 + gid) * SPAD + 2 * tig;
    const float* alp = Alo + (wm * 16 + gid) * SPAD + 2 * tig;
    const float* bhp = BhP + (wn * 32 + gid) * SPAD + 2 * tig;
    const float* blp = BlP + (wn * 32 + gid) * SPAD + 2 * tig;

    for (int ks = 0; ks < NKS; ks++) {
        int k0 = ks * 8;
        // a fragments: rows gid / gid+8, pair (k tig, k tig+4) per LDS.64
        float2 hl = *(const float2*)(ahp + k0);
        float2 hh = *(const float2*)(ahp + 8 * SPAD + k0);
        float2 ll = *(const float2*)(alp + k0);
        float2 lh = *(const float2*)(alp + 8 * SPAD + k0);
        uint32_t ahf[4] = {__float_as_uint(hl.x), __float_as_uint(hh.x),
                           __float_as_uint(hl.y), __float_as_uint(hh.y)};
        uint32_t alf[4] = {__float_as_uint(ll.x), __float_as_uint(lh.x),
                           __float_as_uint(ll.y), __float_as_uint(lh.y)};
#pragma unroll
        for (int nt = 0; nt < 4; nt++) {
            float2 bh2 = *(const float2*)(bhp + nt * 8 * SPAD + k0);
            float2 bl2 = *(const float2*)(blp + nt * 8 * SPAD + k0);
            uint32_t bh[2] = {__float_as_uint(bh2.x), __float_as_uint(bh2.y)};
            uint32_t bl[2] = {__float_as_uint(bl2.x), __float_as_uint(bl2.y)};
            mma8(acc[nt], ahf, bh);
            mma8(acc[nt], ahf, bl);
            mma8(acc[nt], alf, bh);
        }
    }

    __syncthreads();

    // ---- epilogue: transform + sums + triu-direct store ----
    float et = expf(t[0]);
    float* ob = out + (size_t)b * TRI;

    {
        int rb = wm * 16;
        int iA = i0 + rb + gid, iB = iA + 8;
        size_t offA = (size_t)iA * DIM - ((size_t)iA * (iA - 1)) / 2 - iA;
        size_t offB = (size_t)iB * DIM - ((size_t)iB * (iB - 1)) / 2 - iB;
        float diA = di_s[rb + gid];
        float diB = di_s[rb + gid + 8];
        float rsumA = 0.f, rsumB = 0.f;
#pragma unroll
        for (int nt = 0; nt < 4; nt++) {
            int cb = wn * 32 + nt * 8 + tig * 2;
            int jg = j0 + cb;
            float dj0 = dj_s[cb], dj1 = dj_s[cb + 1];
            float* c = acc[nt];

            float q0 = fmaxf(fmaf(-2.f, c[0], diA + dj0), 0.f);
            float q1 = fmaxf(fmaf(-2.f, c[1], diA + dj1), 0.f);
            float q2 = fmaxf(fmaf(-2.f, c[2], diB + dj0), 0.f);
            float q3 = fmaxf(fmaf(-2.f, c[3], diB + dj1), 0.f);
            float v0 = sqrtf(fmaf(et, q0, EPSV));
            float v1 = sqrtf(fmaf(et, q1, EPSV));
            float v2 = sqrtf(fmaf(et, q2, EPSV));
            float v3 = sqrtf(fmaf(et, q3, EPSV));

            rsumA += v0 + v1;
            rsumB += v2 + v3;

            float cs0 = v0 + v2, cs1 = v1 + v3;
#pragma unroll
            for (int o = 4; o <= 16; o <<= 1) {
                cs0 += __shfl_xor_sync(0xffffffffu, cs0, o);
                cs1 += __shfl_xor_sync(0xffffffffu, cs1, o);
            }
            if (gid == 0) {
                atomicAdd(&cs_s[cb], cs0);
                atomicAdd(&cs_s[cb + 1], cs1);
            }

            if (!diag || jg >= iA)     ob[offA + jg]     = v0;
            if (!diag || jg + 1 >= iA) ob[offA + jg + 1] = v1;
            if (!diag || jg >= iB)     ob[offB + jg]     = v2;
            if (!diag || jg + 1 >= iB) ob[offB + jg + 1] = v3;
        }
#pragma unroll
        for (int o = 1; o <= 2; o <<= 1) {
            rsumA += __shfl_xor_sync(0xffffffffu, rsumA, o);
            rsumB += __shfl_xor_sync(0xffffffffu, rsumB, o);
        }
        if (tig == 0) {
            atomicAdd(&rs_s[rb + gid], rsumA);
            atomicAdd(&rs_s[rb + gid + 8], rsumB);
        }
    }
    __syncthreads();

    if (tid < TT) {
        g_sp[tj][b][i0 + tid] = rs_s[tid];
    } else if (!diag && tid < 2 * TT) {
        g_sp[ti][b][j0 + (tid - TT)] = cs_s[tid - TT];
    }
}

// ---------------------------------------------------------------------------
// Sums: per-batch row-sum vector (pre-scaled by 1/dim) + grand mean
// ---------------------------------------------------------------------------
__global__ __launch_bounds__(256)
void sums_kernel() {
    int b = blockIdx.x, tid = threadIdx.x;
    __shared__ float red[256];
    float part = 0.f;
    for (int i = tid; i < DIM; i += 256) {
        float v = g_sp[0][b][i] + g_sp[1][b][i] + g_sp[2][b][i]
                + g_sp[3][b][i] + g_sp[4][b][i];
        g_sb[b * DIM + i] = v * (1.0f / (float)DIM);
        part += v;
    }
    red[tid] = part;
    __syncthreads();
    for (int o = 128; o > 0; o >>= 1) {
        if (tid < o) red[tid] += red[tid + o];
        __syncthreads();
    }
    if (tid == 0) g_gm[b] = red[0] * (1.0f / ((float)DIM * (float)DIM));
}

// ---------------------------------------------------------------------------
// Center apply: in-place streaming RMW of out, one block per (row, batch)
// ---------------------------------------------------------------------------
__global__ __launch_bounds__(128)
void center_apply_kernel(float* __restrict__ out) {
    int i = blockIdx.x, b = blockIdx.y;
    const float* sb = g_sb + b * DIM;
    float corr = g_gm[b] - sb[i];
    float* ob = out + (size_t)b * TRI + ((size_t)i * DIM - ((size_t)i * (i - 1)) / 2);
    int L = DIM - i;
    int tid = threadIdx.x;

    int mis = (int)(((uintptr_t)ob >> 2) & 3);
    int head = (4 - mis) & 3;
    if (head > L) head = L;
    if (tid < head) ob[tid] = ob[tid] - sb[i + tid] + corr;

    int body = (L - head) >> 2;
    float4* vb = (float4*)(ob + head);
    for (int q = tid; q < body; q += 128) {
        float4 v = vb[q];
        int j = i + head + q * 4;
        v.x = v.x - sb[j]     + corr;
        v.y = v.y - sb[j + 1] + corr;
        v.z = v.z - sb[j + 2] + corr;
        v.w = v.w - sb[j + 3] + corr;
        vb[q] = v;
    }
    int done = head + body * 4;
    int tail = L - done;
    if (tid < tail) ob[done + tid] = ob[done + tid] - sb[i + done + tid] + corr;
}

// ---------------------------------------------------------------------------
extern "C" void kernel_launch(void* const* d_in, const int* in_sizes, int n_in,
                              void* d_out, int out_size) {
    const float* x = (const float*)d_in[0];
    const float* t = (const float*)d_in[1];
    float* out = (float*)d_out;

    const int smem1 = 4 * TSZ * (int)sizeof(float);  // 212992 B -> 1 CTA/SM, 32 warps
    cudaFuncSetAttribute(gram_dcov_kernel,
                         cudaFuncAttributeMaxDynamicSharedMemorySize, smem1);

    int c1 = NROWS / 3, c2 = NROWS / 3;
    int c3 = NROWS - c1 - c2;
    norm_kernel<<<(c1 * 32 + 255) / 256, 256>>>(x, 0, c1);
    norm_kernel<<<(c2 * 32 + 255) / 256, 256>>>(x, c1, c2);
    norm_kernel<<<(c3 * 32 + 255) / 256, 256>>>(x, c1 + c2, c3);
    gram_dcov_kernel<<<dim3(NPAIR, BB), 1024, smem1>>>(x, t, out);
    sums_kernel<<<BB, 256>>>();
    center_apply_kernel<<<dim3(DIM, BB), 128>>>(out);
}

// round 13
// speedup vs baseline: 1.5401x; 1.5401x over previous
#include <cuda_runtime.h>
#include <math.h>
#include <cstdint>

#define BB 64
#define DIM 640
#define MK 100
#define NKS 13
#define TT 128
#define NT 5            // DIM / TT
#define NPAIR 15        // upper tile pairs
#define TRI 205120      // 640*641/2
#define EPSV 1e-5f
#define SPAD 104        // EVEN stride: permuted LDS.64 frag loads conflict-free
#define TSZ (TT * SPAD)
#define NROWS (BB * DIM)

// ---- scratch (static device arrays: allocation-free) ----
__device__ float g_sp[NT][BB][DIM];   // row-sum slots (exactly-once writes)
__device__ float g_d[NROWS];          // squared norms
__device__ float g_sb[NROWS];         // per-batch row sums, pre-scaled by 1/dim
__device__ float g_gm[BB];            // per-batch grand mean

// ---------------------------------------------------------------------------
__device__ __forceinline__ uint32_t f2tf32(float v) {
    uint32_t r;
    asm("cvt.rna.tf32.f32 %0, %1;" : "=r"(r) : "f"(v));
    return r;
}
__device__ __forceinline__ void mma8(float* c, const uint32_t* a, const uint32_t* b) {
    asm volatile(
        "mma.sync.aligned.m16n8k8.row.col.f32.tf32.tf32.f32 "
        "{%0,%1,%2,%3}, {%4,%5,%6,%7}, {%8,%9}, {%0,%1,%2,%3};"
        : "+f"(c[0]), "+f"(c[1]), "+f"(c[2]), "+f"(c[3])
        : "r"(a[0]), "r"(a[1]), "r"(a[2]), "r"(a[3]), "r"(b[0]), "r"(b[1]));
}
// permuted position of k within its 8-block: order [0,4,1,5,2,6,3,7]
__device__ __forceinline__ int kperm(int k) {
    return (k & ~7) + 2 * (k & 3) + ((k & 7) >> 2);
}

// ---------------------------------------------------------------------------
// Norms: one warp per x-row (coalesced), split over batch thirds
// ---------------------------------------------------------------------------
__global__ void norm_kernel(const float* __restrict__ x, int row0, int nrows) {
    int w = (blockIdx.x * 256 + threadIdx.x) >> 5;
    int lane = threadIdx.x & 31;
    if (w >= nrows) return;
    const float* xr = x + (size_t)(row0 + w) * MK;
    float s = 0.f;
#pragma unroll
    for (int k = lane; k < MK; k += 32) { float v = xr[k]; s = fmaf(v, v, s); }
#pragma unroll
    for (int o = 16; o >= 1; o >>= 1) s += __shfl_xor_sync(0xffffffffu, s, o);
    if (lane == 0) g_d[row0 + w] = s;
}

// ---------------------------------------------------------------------------
// Gram: R8 geometry (256 thr, 64x32 warp tiles, 2 CTA/SM, 16 indep acc chains)
// + permuted-k LDS.64 fragment loads + single-cvt Dekker tf32 reg split.
// ---------------------------------------------------------------------------
__global__ __launch_bounds__(256, 2)
void gram_dcov_kernel(const float* __restrict__ x, const float* __restrict__ t,
                      float* __restrict__ out) {
    int p = blockIdx.x, b = blockIdx.y;
    int ti = 0, rem = p;
    while (rem >= NT - ti) { rem -= NT - ti; ti++; }
    int tj = ti + rem;
    int i0 = ti * TT, j0 = tj * TT;
    bool diag = (ti == tj);

    extern __shared__ float sm[];
    float* A = sm;
    float* B = A + TSZ;

    __shared__ float di_s[TT], dj_s[TT], rs_s[TT], cs_s[TT];

    int tid = threadIdx.x;
    if (tid < TT) { rs_s[tid] = 0.f; cs_s[tid] = 0.f; }

    const float* xb = x + (size_t)b * DIM * MK;

    // ---- stage fp32 tiles into permuted-k layout (zeros for k in [100,104)) ----
    {
        const float* srcA = xb + (size_t)i0 * MK;
        for (int idx = tid; idx < TT * SPAD; idx += 256) {
            int r = idx / SPAD, k = idx - r * SPAD;
            float v = (k < MK) ? srcA[r * MK + k] : 0.f;
            A[r * SPAD + kperm(k)] = v;
        }
        if (!diag) {
            const float* srcB = xb + (size_t)j0 * MK;
            for (int idx = tid; idx < TT * SPAD; idx += 256) {
                int r = idx / SPAD, k = idx - r * SPAD;
                float v = (k < MK) ? srcB[r * MK + k] : 0.f;
                B[r * SPAD + kperm(k)] = v;
            }
        }
    }
    // preload norms (L2-hot)
    {
        const float* dbase = g_d + b * DIM;
        if (tid < TT) di_s[tid] = dbase[i0 + tid];
        else dj_s[tid - TT] = dbase[j0 + (tid - TT)];
    }
    const float* Bp = diag ? A : B;
    __syncthreads();

    // warp layout: 2(m) x 4(n); warp tile 64 rows x 32 cols
    int wid = tid >> 5, lane = tid & 31;
    int wm = wid & 1, wn = wid >> 1;
    int gid = lane >> 2, tig = lane & 3;

    float acc[4][4][4];
#pragma unroll
    for (int mt = 0; mt < 4; mt++)
#pragma unroll
        for (int nt = 0; nt < 4; nt++)
#pragma unroll
            for (int q = 0; q < 4; q++) acc[mt][nt][q] = 0.f;

    const float* aptr = A + (wm * 64 + gid) * SPAD + 2 * tig;
    const float* bptr = Bp + (wn * 32 + gid) * SPAD + 2 * tig;

    for (int ks = 0; ks < NKS; ks++) {
        int k0 = ks * 8;
        // b fragments: 4 nt blocks, one LDS.64 each -> hi/lo in regs
        uint32_t bhi[4][2], blo[4][2];
#pragma unroll
        for (int nt = 0; nt < 4; nt++) {
            float2 bq = *(const float2*)(bptr + nt * 8 * SPAD + k0);
            bhi[nt][0] = f2tf32(bq.x);
            bhi[nt][1] = f2tf32(bq.y);
            blo[nt][0] = __float_as_uint(bq.x - __uint_as_float(bhi[nt][0]));
            blo[nt][1] = __float_as_uint(bq.y - __uint_as_float(bhi[nt][1]));
        }
        // a fragments: 4 m tiles, two LDS.64 each (rows gid, gid+8)
#pragma unroll
        for (int mt = 0; mt < 4; mt++) {
            float2 rl = *(const float2*)(aptr + (mt * 16) * SPAD + k0);
            float2 rh = *(const float2*)(aptr + (mt * 16 + 8) * SPAD + k0);
            uint32_t ahi[4], alo[4];
            ahi[0] = f2tf32(rl.x); alo[0] = __float_as_uint(rl.x - __uint_as_float(ahi[0]));
            ahi[1] = f2tf32(rh.x); alo[1] = __float_as_uint(rh.x - __uint_as_float(ahi[1]));
            ahi[2] = f2tf32(rl.y); alo[2] = __float_as_uint(rl.y - __uint_as_float(ahi[2]));
            ahi[3] = f2tf32(rh.y); alo[3] = __float_as_uint(rh.y - __uint_as_float(ahi[3]));
#pragma unroll
            for (int nt = 0; nt < 4; nt++) {
                mma8(acc[mt][nt], ahi, bhi[nt]);
                mma8(acc[mt][nt], ahi, blo[nt]);
                mma8(acc[mt][nt], alo, bhi[nt]);
            }
        }
    }

    __syncthreads();

    // ---- epilogue: transform + sums + triu-direct store ----
    float et = expf(t[0]);
    float* ob = out + (size_t)b * TRI;

#pragma unroll
    for (int mt = 0; mt < 4; mt++) {
        int rb = wm * 64 + mt * 16;
        int iA = i0 + rb + gid, iB = iA + 8;
        size_t offA = (size_t)iA * DIM - ((size_t)iA * (iA - 1)) / 2 - iA;
        size_t offB = (size_t)iB * DIM - ((size_t)iB * (iB - 1)) / 2 - iB;
        float diA = di_s[rb + gid];
        float diB = di_s[rb + gid + 8];
        float rsumA = 0.f, rsumB = 0.f;
#pragma unroll
        for (int nt = 0; nt < 4; nt++) {
            int cb = wn * 32 + nt * 8 + tig * 2;
            int jg = j0 + cb;
            float dj0 = dj_s[cb], dj1 = dj_s[cb + 1];
            float* c = acc[mt][nt];

            float q0 = fmaxf(fmaf(-2.f, c[0], diA + dj0), 0.f);
            float q1 = fmaxf(fmaf(-2.f, c[1], diA + dj1), 0.f);
            float q2 = fmaxf(fmaf(-2.f, c[2], diB + dj0), 0.f);
            float q3 = fmaxf(fmaf(-2.f, c[3], diB + dj1), 0.f);
            float v0 = sqrtf(fmaf(et, q0, EPSV));
            float v1 = sqrtf(fmaf(et, q1, EPSV));
            float v2 = sqrtf(fmaf(et, q2, EPSV));
            float v3 = sqrtf(fmaf(et, q3, EPSV));

            rsumA += v0 + v1;
            rsumB += v2 + v3;

            float cs0 = v0 + v2, cs1 = v1 + v3;
#pragma unroll
            for (int o = 4; o <= 16; o <<= 1) {
                cs0 += __shfl_xor_sync(0xffffffffu, cs0, o);
                cs1 += __shfl_xor_sync(0xffffffffu, cs1, o);
            }
            if (gid == 0) {
                atomicAdd(&cs_s[cb], cs0);
                atomicAdd(&cs_s[cb + 1], cs1);
            }

            if (!diag || jg >= iA)     ob[offA + jg]     = v0;
            if (!diag || jg + 1 >= iA) ob[offA + jg + 1] = v1;
            if (!diag || jg >= iB)     ob[offB + jg]     = v2;
            if (!diag || jg + 1 >= iB) ob[offB + jg + 1] = v3;
        }
#pragma unroll
        for (int o = 1; o <= 2; o <<= 1) {
            rsumA += __shfl_xor_sync(0xffffffffu, rsumA, o);
            rsumB += __shfl_xor_sync(0xffffffffu, rsumB, o);
        }
        if (tig == 0) {
            atomicAdd(&rs_s[rb + gid], rsumA);
            atomicAdd(&rs_s[rb + gid + 8], rsumB);
        }
    }
    __syncthreads();

    if (tid < TT) {
        g_sp[tj][b][i0 + tid] = rs_s[tid];
    } else if (!diag) {
        g_sp[ti][b][j0 + (tid - TT)] = cs_s[tid - TT];
    }
}

// ---------------------------------------------------------------------------
// Sums: per-batch row-sum vector (pre-scaled by 1/dim) + grand mean
// ---------------------------------------------------------------------------
__global__ __launch_bounds__(256)
void sums_kernel() {
    int b = blockIdx.x, tid = threadIdx.x;
    __shared__ float red[256];
    float part = 0.f;
    for (int i = tid; i < DIM; i += 256) {
        float v = g_sp[0][b][i] + g_sp[1][b][i] + g_sp[2][b][i]
                + g_sp[3][b][i] + g_sp[4][b][i];
        g_sb[b * DIM + i] = v * (1.0f / (float)DIM);
        part += v;
    }
    red[tid] = part;
    __syncthreads();
    for (int o = 128; o > 0; o >>= 1) {
        if (tid < o) red[tid] += red[tid + o];
        __syncthreads();
    }
    if (tid == 0) g_gm[b] = red[0] * (1.0f / ((float)DIM * (float)DIM));
}

// ---------------------------------------------------------------------------
// Center apply: in-place streaming RMW of out, one block per (row, batch)
// ---------------------------------------------------------------------------
__global__ __launch_bounds__(128)
void center_apply_kernel(float* __restrict__ out) {
    int i = blockIdx.x, b = blockIdx.y;
    const float* sb = g_sb + b * DIM;
    float corr = g_gm[b] - sb[i];
    float* ob = out + (size_t)b * TRI + ((size_t)i * DIM - ((size_t)i * (i - 1)) / 2);
    int L = DIM - i;
    int tid = threadIdx.x;

    int mis = (int)(((uintptr_t)ob >> 2) & 3);
    int head = (4 - mis) & 3;
    if (head > L) head = L;
    if (tid < head) ob[tid] = ob[tid] - sb[i + tid] + corr;

    int body = (L - head) >> 2;
    float4* vb = (float4*)(ob + head);
    for (int q = tid; q < body; q += 128) {
        float4 v = vb[q];
        int j = i + head + q * 4;
        v.x = v.x - sb[j]     + corr;
        v.y = v.y - sb[j + 1] + corr;
        v.z = v.z - sb[j + 2] + corr;
        v.w = v.w - sb[j + 3] + corr;
        vb[q] = v;
    }
    int done = head + body * 4;
    int tail = L - done;
    if (tid < tail) ob[done + tid] = ob[done + tid] - sb[i + done + tid] + corr;
}

// ---------------------------------------------------------------------------
extern "C" void kernel_launch(void* const* d_in, const int* in_sizes, int n_in,
                              void* d_out, int out_size) {
    const float* x = (const float*)d_in[0];
    const float* t = (const float*)d_in[1];
    float* out = (float*)d_out;

    const int smem1 = 2 * TSZ * (int)sizeof(float);  // 106496 B -> 2 CTAs/SM
    cudaFuncSetAttribute(gram_dcov_kernel,
                         cudaFuncAttributeMaxDynamicSharedMemorySize, smem1);

    int c1 = NROWS / 3, c2 = NROWS / 3;
    int c3 = NROWS - c1 - c2;
    norm_kernel<<<(c1 * 32 + 255) / 256, 256>>>(x, 0, c1);
    norm_kernel<<<(c2 * 32 + 255) / 256, 256>>>(x, c1, c2);
    norm_kernel<<<(c3 * 32 + 255) / 256, 256>>>(x, c1 + c2, c3);
    gram_dcov_kernel<<<dim3(NPAIR, BB), 256, smem1>>>(x, t, out);
    sums_kernel<<<BB, 256>>>();
    center_apply_kernel<<<dim3(DIM, BB), 128>>>(out);
}